// round 5
// baseline (speedup 1.0000x reference)
#include <cuda_runtime.h>
#include <cstdint>

#define TSTEPS 512
#define BSZ    256
#define DIN    128
#define HID    256
#define NPROTO 128
#define DHTOT  384
#define NB     8            // batches per cluster
#define CSZ    4            // CTAs per cluster
#define NTHR   512
#define NCTA   128

__device__ float4 g_Wpack[NPROTO][HID];          // [p][h] = {wf, wi, wg, wo}
__device__ float4 g_protoPack[DHTOT/4][NPROTO];  // [q][p] = proto[p][4q..4q+3]
__device__ float  g_pn2[NPROTO];

typedef unsigned long long u64;

// ---------------- smem layout (bytes) ----------------
// PROT: [24 q][128 p] float4                    49152
// KD  : [128 p][10 u64] ({k,k} dup, slots 0..7) 10240
// DOT : [2 buf][4 r][4 pr][128 p] u64           32768
// CN2 : [2 buf][4 r][4 pr] u64                    256
// CMB : [4 pr][96 d] u64 ({b_even,b_odd})        3072
#define PROT_OFF 0
#define KD_OFF   49152
#define DOT_OFF  59392
#define CN2_OFF  92160
#define CMB_OFF  92416
#define SMEM_TOTAL 95488

__device__ __forceinline__ u64 pk2(float lo, float hi){
    u64 r; asm("mov.b64 %0, {%1,%2};" : "=l"(r) : "f"(lo), "f"(hi)); return r;
}
__device__ __forceinline__ void upk2(u64 v, float& lo, float& hi){
    asm("mov.b64 {%0,%1}, %2;" : "=f"(lo), "=f"(hi) : "l"(v));
}
__device__ __forceinline__ u64 ffma2(u64 a, u64 b, u64 c){
    u64 d; asm("fma.rn.f32x2 %0, %1, %2, %3;" : "=l"(d) : "l"(a), "l"(b), "l"(c)); return d;
}
__device__ __forceinline__ u64 add2(u64 a, u64 b){
    u64 d; asm("add.rn.f32x2 %0, %1, %2;" : "=l"(d) : "l"(a), "l"(b)); return d;
}
__device__ __forceinline__ float sigmf(float x){
    return __fdividef(1.f, 1.f + __expf(-x));
}
__device__ __forceinline__ float tanhf_(float x){
    return 1.f - __fdividef(2.f, __expf(2.f*x) + 1.f);
}
__device__ __forceinline__ uint32_t smem_u32(const void* p){
    uint32_t a;
    asm("{ .reg .u64 t; cvta.to.shared.u64 t, %1; cvt.u32.u64 %0, t; }" : "=r"(a) : "l"(p));
    return a;
}
__device__ __forceinline__ uint32_t ctarank(){
    uint32_t r; asm("mov.u32 %0, %%cluster_ctarank;" : "=r"(r)); return r;
}
__device__ __forceinline__ uint32_t mapa_u32(uint32_t local, uint32_t rank){
    uint32_t r; asm("mapa.shared::cluster.u32 %0, %1, %2;" : "=r"(r) : "r"(local), "r"(rank));
    return r;
}
__device__ __forceinline__ void st_cl64(uint32_t addr, u64 v){
    asm volatile("st.shared::cluster.b64 [%0], %1;" :: "r"(addr), "l"(v) : "memory");
}
__device__ __forceinline__ void cl_arrive(){
    asm volatile("barrier.cluster.arrive.aligned;" ::: "memory");
}
__device__ __forceinline__ void cl_wait(){
    asm volatile("barrier.cluster.wait.aligned;"   ::: "memory");
}
__device__ __forceinline__ u64 shfl_xor64(u64 v, int off){
    uint32_t lo = (uint32_t)v, hi = (uint32_t)(v >> 32);
    lo = __shfl_xor_sync(0xffffffffu, lo, off);
    hi = __shfl_xor_sync(0xffffffffu, hi, off);
    return ((u64)hi << 32) | lo;
}

__global__ void pack_kernel(const float* __restrict__ proto,
                            const float* __restrict__ Wf, const float* __restrict__ Wi,
                            const float* __restrict__ Wg, const float* __restrict__ Wo){
    int idx = blockIdx.x * blockDim.x + threadIdx.x;
    if (idx < HID*NPROTO){
        int h = idx >> 7, pp = idx & (NPROTO-1);
        g_Wpack[pp][h] = make_float4(Wf[idx], Wi[idx], Wg[idx], Wo[idx]);
    }
    if (idx < (DHTOT/4)*NPROTO){
        int q = idx >> 7, pp = idx & (NPROTO-1);
        const float* pr = proto + pp*DHTOT + 4*q;
        g_protoPack[q][pp] = make_float4(pr[0], pr[1], pr[2], pr[3]);
    }
    if (idx < NPROTO){
        float s = 0.f;
        for (int d = 0; d < DHTOT; ++d){ float v = proto[idx*DHTOT + d]; s = fmaf(v, v, s); }
        g_pn2[idx] = s;
    }
}

extern __shared__ char sm[];

__global__ void __cluster_dims__(CSZ,1,1) __launch_bounds__(NTHR, 1)
qlstm_kernel(const float* __restrict__ x,
             const float* __restrict__ bf, const float* __restrict__ bi,
             const float* __restrict__ bg, const float* __restrict__ bo,
             float* __restrict__ out){
    const int tid  = threadIdx.x;
    const int lane = tid & 31;
    const int wrp  = tid >> 5;
    const uint32_t rank = ctarank();
    const int bbase = (blockIdx.x >> 2) * NB;
    const uint32_t base = smem_u32(sm);

    float4* PROT = reinterpret_cast<float4*>(sm + PROT_OFF);  // [q][p]
    u64*    KD   = reinterpret_cast<u64*>(sm + KD_OFF);       // [p][10]
    const ulonglong2* KDv2 = reinterpret_cast<const ulonglong2*>(sm + KD_OFF);
    u64*    DOT  = reinterpret_cast<u64*>(sm + DOT_OFF);
    u64*    CN2  = reinterpret_cast<u64*>(sm + CN2_OFF);
    u64*    CMB  = reinterpret_cast<u64*>(sm + CMB_OFF);      // [pr][96 d]
    float*  CMBF = reinterpret_cast<float*>(sm + CMB_OFF);

    // ---------- per-thread roles ----------
    // dist: dc = lane bit0 (d-half), pDd = 16*(wrp&7) + (lane>>1), prh = wrp>>3
    const int dcD = lane & 1;
    const int pDd = ((wrp & 7) << 4) + (lane >> 1);
    const int prh = wrp >> 3;
    // k: pK = tid&127, prK = tid>>7
    const int pK  = tid & 127;
    const int prK = tid >> 7;
    // gate: pc = lane&7 (== batch after reduce), hL = wrp*4 + (lane>>3)
    const int pcB = lane & 7;
    const int hL  = (wrp << 2) + (lane >> 3);
    const int hglob = (int)rank*64 + hL;

    // ---------- preamble ----------
    // prototype d-slice -> smem: q<8 -> x-chunk 8*rank+q, else h-chunk 32+16*rank+(q-8)
    #pragma unroll
    for (int i = 0; i < 6; ++i){
        int idx = tid + i*NTHR;
        int q = idx >> 7, p = idx & 127;
        int Q = (q < 8) ? (8*(int)rank + q) : (32 + 16*(int)rank + (q - 8));
        PROT[q*128 + p] = g_protoPack[Q][p];
    }
    // persistent register weights: thread (hL, pcB) holds p = j*8 + pcB, j=0..15
    u64 wFI[16], wGO[16];
    #pragma unroll
    for (int j = 0; j < 16; ++j){
        float4 w = g_Wpack[j*8 + pcB][hglob];
        wFI[j] = pk2(w.x, w.y);
        wGO[j] = pk2(w.z, w.w);
    }
    // zero hv region of CMB (slots 32..95 per pair)
    if (tid < 256){
        int pr = tid >> 6, sl = tid & 63;
        CMB[pr*96 + 32 + sl] = 0ull;
    }
    // load x(0) slice: d = 32*rank + dl
    if (tid < 256){
        int b = tid >> 5, dl = tid & 31;
        CMBF[((b >> 1)*96 + dl)*2 + (b & 1)] =
            __ldcg(&x[((size_t)0*BSZ + bbase + b)*DIN + rank*32 + dl]);
    }

    const u64 bFI = pk2(bf[hglob], bi[hglob]);
    const u64 bGO = pk2(bg[hglob], bo[hglob]);
    const float pn2v = g_pn2[pK];

    // hoisted DSMEM addresses: my 2 dist-partial slots + cn2 slot in every rank
    uint32_t dotA0[CSZ], dotA1[CSZ], cnAddr[CSZ];
    {
        uint32_t d0 = base + DOT_OFF + (uint32_t)((((rank*4) + 2*prh    )*128 + pDd)*8);
        uint32_t d1 = base + DOT_OFF + (uint32_t)((((rank*4) + 2*prh + 1)*128 + pDd)*8);
        uint32_t c0 = base + CN2_OFF + (uint32_t)((rank*4 + (tid >> 5))*8);  // cn2 role (tid<128)
        #pragma unroll
        for (uint32_t r = 0; r < CSZ; ++r){
            dotA0[r]  = mapa_u32(d0, r);
            dotA1[r]  = mapa_u32(d1, r);
            cnAddr[r] = mapa_u32(c0, r);
        }
    }

    float cx = 0.f, hv = 0.f;

    __syncthreads();
    cl_arrive(); cl_wait();             // init visible cluster-wide

    for (int t = 0; t < TSTEPS; ++t){
        const uint32_t bufDot = (uint32_t)(t & 1) * 16384u;
        const uint32_t bufCn  = (uint32_t)(t & 1) * 128u;
        const int      bufU   = (t & 1) * 2048;
        const int      bufC   = (t & 1) * 16;

        __syncthreads();                // S1: x(t) + hv(t-1) visible locally

        // ---- dist partial: thread=(pDd, dc, prh pair), 48 d each ----
        {
            u64 a0A = 0ull, a0B = 0ull, a1A = 0ull, a1B = 0ull;
            const float4* pp  = PROT + dcD*12*128 + pDd;
            const u64*    cb0 = CMB + (2*prh    )*96 + dcD*48;
            const u64*    cb1 = CMB + (2*prh + 1)*96 + dcD*48;
            #pragma unroll
            for (int qq = 0; qq < 12; ++qq){
                float4 pv = pp[qq*128];
                u64 v0 = pk2(pv.x, pv.x), v1 = pk2(pv.y, pv.y);
                u64 v2 = pk2(pv.z, pv.z), v3 = pk2(pv.w, pv.w);
                ulonglong2 cA0 = *reinterpret_cast<const ulonglong2*>(cb0 + 4*qq);
                ulonglong2 cB0 = *reinterpret_cast<const ulonglong2*>(cb0 + 4*qq + 2);
                ulonglong2 cA1 = *reinterpret_cast<const ulonglong2*>(cb1 + 4*qq);
                ulonglong2 cB1 = *reinterpret_cast<const ulonglong2*>(cb1 + 4*qq + 2);
                a0A = ffma2(cA0.x, v0, a0A); a0B = ffma2(cA0.y, v1, a0B);
                a0A = ffma2(cB0.x, v2, a0A); a0B = ffma2(cB0.y, v3, a0B);
                a1A = ffma2(cA1.x, v0, a1A); a1B = ffma2(cA1.y, v1, a1B);
                a1A = ffma2(cB1.x, v2, a1A); a1B = ffma2(cB1.y, v3, a1B);
            }
            u64 a0 = add2(a0A, a0B);  a0 = add2(a0, shfl_xor64(a0, 1));
            u64 a1 = add2(a1A, a1B);  a1 = add2(a1, shfl_xor64(a1, 1));
            if (dcD == 0){
                #pragma unroll
                for (int r = 0; r < CSZ; ++r){
                    st_cl64(dotA0[r] + bufDot, a0);
                    st_cl64(dotA1[r] + bufDot, a1);
                }
            }
        }

        // ---- cn2 partial over slice (warps 0-3: pr = wrp) ----
        if (tid < 128){
            const u64* cb = CMB + wrp*96;
            u64 c0 = cb[lane], c1 = cb[lane+32], c2 = cb[lane+64];
            u64 a = ffma2(c0, c0, ffma2(c1, c1, ffma2(c2, c2, 0ull)));
            #pragma unroll
            for (int off = 16; off; off >>= 1)
                a = add2(a, shfl_xor64(a, off));
            if (lane == 0){
                #pragma unroll
                for (int r = 0; r < CSZ; ++r) st_cl64(cnAddr[r] + bufCn, a);
            }
        }
        __syncthreads();                // S2: local reads of CMB-x done

        cl_arrive();                    // release my partials

        // ---- prefetch x(t+1) while peers finish ----
        if (t + 1 < TSTEPS && tid < 256){
            int b = tid >> 5, dl = tid & 31;
            CMBF[((b >> 1)*96 + dl)*2 + (b & 1)] =
                __ldcg(&x[((size_t)(t+1)*BSZ + bbase + b)*DIN + rank*32 + dl]);
        }
        cl_wait();                      // acquire all ranks' partials

        // ---- k: thread=(pK, prK), reduce 4 rank-partials, 2 exps ----
        {
            const u64* db = DOT + bufU;
            u64 ds =        db[(0*4 + prK)*128 + pK];
            ds = add2(ds,   db[(1*4 + prK)*128 + pK]);
            ds = add2(ds,   db[(2*4 + prK)*128 + pK]);
            ds = add2(ds,   db[(3*4 + prK)*128 + pK]);
            const u64* cn = CN2 + bufC;
            u64 cs = add2(add2(cn[0*4 + prK], cn[1*4 + prK]),
                          add2(cn[2*4 + prK], cn[3*4 + prK]));
            float d0, d1, c0, c1;
            upk2(ds, d0, d1); upk2(cs, c0, c1);
            float k0 = __expf(2.f*d0 - pn2v - c0);
            float k1 = __expf(2.f*d1 - pn2v - c1);
            ulonglong2 kk; kk.x = pk2(k0, k0); kk.y = pk2(k1, k1);
            *reinterpret_cast<ulonglong2*>(KD + pK*10 + 2*prK) = kk;
        }
        __syncthreads();                // S3: KD ready

        // ---- gate GEMM: thread=(hL, pcB), p = j*8+pcB, all 8 batches ----
        {
            u64 F[8], G[8];
            #pragma unroll
            for (int b = 0; b < 8; ++b){ F[b] = 0ull; G[b] = 0ull; }
            const ulonglong2* kdp = KDv2 + pcB*5;   // KD row stride = 10 u64 = 5 u128
            #pragma unroll
            for (int j = 0; j < 16; ++j){
                ulonglong2 kA = kdp[j*40 + 0];      // b0,b1 ({k,k} each)
                ulonglong2 kB = kdp[j*40 + 1];      // b2,b3
                ulonglong2 kC = kdp[j*40 + 2];      // b4,b5
                ulonglong2 kE = kdp[j*40 + 3];      // b6,b7
                F[0] = ffma2(wFI[j], kA.x, F[0]);  G[0] = ffma2(wGO[j], kA.x, G[0]);
                F[1] = ffma2(wFI[j], kA.y, F[1]);  G[1] = ffma2(wGO[j], kA.y, G[1]);
                F[2] = ffma2(wFI[j], kB.x, F[2]);  G[2] = ffma2(wGO[j], kB.x, G[2]);
                F[3] = ffma2(wFI[j], kB.y, F[3]);  G[3] = ffma2(wGO[j], kB.y, G[3]);
                F[4] = ffma2(wFI[j], kC.x, F[4]);  G[4] = ffma2(wGO[j], kC.x, G[4]);
                F[5] = ffma2(wFI[j], kC.y, F[5]);  G[5] = ffma2(wGO[j], kC.y, G[5]);
                F[6] = ffma2(wFI[j], kE.x, F[6]);  G[6] = ffma2(wGO[j], kE.x, G[6]);
                F[7] = ffma2(wFI[j], kE.y, F[7]);  G[7] = ffma2(wGO[j], kE.y, G[7]);
            }
            // butterfly reduce over the 8 pc lanes; lane ends with b = pcB
            #pragma unroll
            for (int b = 0; b < 8; ++b){
                F[b] = add2(F[b], shfl_xor64(F[b], 4));
                G[b] = add2(G[b], shfl_xor64(G[b], 4));
            }
            const bool hi4 = (pcB & 4) != 0;
            u64 FA[4], GA[4];
            #pragma unroll
            for (int i = 0; i < 4; ++i){
                FA[i] = hi4 ? F[i+4] : F[i];
                GA[i] = hi4 ? G[i+4] : G[i];
            }
            #pragma unroll
            for (int i = 0; i < 4; ++i){
                FA[i] = add2(FA[i], shfl_xor64(FA[i], 2));
                GA[i] = add2(GA[i], shfl_xor64(GA[i], 2));
            }
            const bool hi2 = (pcB & 2) != 0;
            u64 FB[2], GB[2];
            #pragma unroll
            for (int i = 0; i < 2; ++i){
                FB[i] = hi2 ? FA[i+2] : FA[i];
                GB[i] = hi2 ? GA[i+2] : GA[i];
            }
            #pragma unroll
            for (int i = 0; i < 2; ++i){
                FB[i] = add2(FB[i], shfl_xor64(FB[i], 1));
                GB[i] = add2(GB[i], shfl_xor64(GB[i], 1));
            }
            const bool hi1 = (pcB & 1) != 0;
            u64 Fa = add2(hi1 ? FB[1] : FB[0], bFI);
            u64 Ga = add2(hi1 ? GB[1] : GB[0], bGO);

            // ---- activations + cell update: this thread owns (b=pcB, h=hglob) ----
            float fp, ip, gp, op;
            upk2(Fa, fp, ip); upk2(Ga, gp, op);
            float fv = sigmf(fp), iv = sigmf(ip), gv = tanhf_(gp), ov = sigmf(op);
            cx = fv*cx + iv*gv;
            hv = ov * tanhf_(cx);
            CMBF[((pcB >> 1)*96 + 32 + hL)*2 + (pcB & 1)] = hv;
            out[((size_t)t*BSZ + bbase + pcB)*HID + hglob] = hv;
        }
        // loop-top S1 orders hv/x(t+1); DOT double-buffer + the single cluster
        // barrier handles cross-CTA WAR.
    }

    // ---- finals: hx, cx appended after outputs ----
    {
        const size_t TBH = (size_t)TSTEPS * BSZ * HID;
        const size_t BH  = (size_t)BSZ * HID;
        out[TBH + (size_t)(bbase + pcB)*HID + hglob] = hv;
        out[TBH + BH + (size_t)(bbase + pcB)*HID + hglob] = cx;
    }
}

extern "C" void kernel_launch(void* const* d_in, const int* in_sizes, int n_in,
                              void* d_out, int out_size){
    (void)in_sizes; (void)n_in; (void)out_size;
    const float* inputs = (const float*)d_in[0];
    const float* proto  = (const float*)d_in[1];
    const float* Wf     = (const float*)d_in[2];
    const float* bf     = (const float*)d_in[3];
    const float* Wi     = (const float*)d_in[4];
    const float* bi     = (const float*)d_in[5];
    const float* Wg     = (const float*)d_in[6];
    const float* bg     = (const float*)d_in[7];
    const float* Wo     = (const float*)d_in[8];
    const float* bo     = (const float*)d_in[9];
    float* out = (float*)d_out;

    cudaFuncSetAttribute(qlstm_kernel,
                         cudaFuncAttributeMaxDynamicSharedMemorySize, SMEM_TOTAL);

    pack_kernel<<<(HID*NPROTO + 511)/512, 512>>>(proto, Wf, Wi, Wg, Wo);
    qlstm_kernel<<<NCTA, NTHR, SMEM_TOTAL>>>(inputs, bf, bi, bg, bo, out);
}

// round 6
// speedup vs baseline: 1.3558x; 1.3558x over previous
#include <cuda_runtime.h>
#include <cstdint>

#define TSTEPS 512
#define BSZ    256
#define DIN    128
#define HID    256
#define NPROTO 128
#define DHTOT  384
#define NB     8            // batches per cluster
#define CSZ    4            // CTAs per cluster
#define NTHR   512
#define NCTA   128

__device__ float4 g_Wpack[NPROTO][HID];          // [p][h] = {wf, wi, wg, wo}
__device__ float4 g_protoPack[DHTOT/4][NPROTO];  // [q][p] = proto[p][4q..4q+3]
__device__ float  g_pn2[NPROTO];                 // full ||proto||^2
__device__ unsigned long long g_PP[DIN][NPROTO/2];   // [d][pp] = {proto[2pp][d], proto[2pp+1][d]}
__device__ float  g_DOTX[(size_t)TSTEPS*BSZ*NPROTO]; // dot(x,proto_x) - 0.5*||x||^2

typedef unsigned long long u64;

// ---------------- qlstm smem layout (bytes) ----------------
// PROT: [16 q][128 p] float4      32768  (this CTA's h-quarter of prototypes)
// PG  : [8 pc][8 b][2 fi][64 h]   65536
// KD  : [128 p][10 u64]           10240  ({k,k} dup, pad 8->10 for banks)
// DOT : [2 buf][4 r][4 pr][128 p] 32768
// PD  : [4 dc][4 pr][128 p] u64   16384
// CN2 : [2 buf][4 r][4 pr] u64      256
// CMB : [4 pr][64 h] u64           2048  (hv only; {b_even,b_odd})
#define PROT_OFF 0
#define PG_OFF   32768
#define KD_OFF   98304
#define DOT_OFF  108544
#define PD_OFF   141312
#define CN2_OFF  157696
#define CMB_OFF  157952
#define SMEM_TOTAL 160000

__device__ __forceinline__ u64 pk2(float lo, float hi){
    u64 r; asm("mov.b64 %0, {%1,%2};" : "=l"(r) : "f"(lo), "f"(hi)); return r;
}
__device__ __forceinline__ void upk2(u64 v, float& lo, float& hi){
    asm("mov.b64 {%0,%1}, %2;" : "=f"(lo), "=f"(hi) : "l"(v));
}
__device__ __forceinline__ u64 ffma2(u64 a, u64 b, u64 c){
    u64 d; asm("fma.rn.f32x2 %0, %1, %2, %3;" : "=l"(d) : "l"(a), "l"(b), "l"(c)); return d;
}
__device__ __forceinline__ u64 add2(u64 a, u64 b){
    u64 d; asm("add.rn.f32x2 %0, %1, %2;" : "=l"(d) : "l"(a), "l"(b)); return d;
}
__device__ __forceinline__ float sigmf(float x){
    return __fdividef(1.f, 1.f + __expf(-x));
}
__device__ __forceinline__ float tanhf_(float x){
    return 1.f - __fdividef(2.f, __expf(2.f*x) + 1.f);
}
__device__ __forceinline__ uint32_t smem_u32(const void* p){
    uint32_t a;
    asm("{ .reg .u64 t; cvta.to.shared.u64 t, %1; cvt.u32.u64 %0, t; }" : "=r"(a) : "l"(p));
    return a;
}
__device__ __forceinline__ uint32_t ctarank(){
    uint32_t r; asm("mov.u32 %0, %%cluster_ctarank;" : "=r"(r)); return r;
}
__device__ __forceinline__ uint32_t mapa_u32(uint32_t local, uint32_t rank){
    uint32_t r; asm("mapa.shared::cluster.u32 %0, %1, %2;" : "=r"(r) : "r"(local), "r"(rank));
    return r;
}
__device__ __forceinline__ void st_cl64(uint32_t addr, u64 v){
    asm volatile("st.shared::cluster.b64 [%0], %1;" :: "r"(addr), "l"(v) : "memory");
}
__device__ __forceinline__ void cl_arrive(){
    asm volatile("barrier.cluster.arrive.aligned;" ::: "memory");
}
__device__ __forceinline__ void cl_wait(){
    asm volatile("barrier.cluster.wait.aligned;"   ::: "memory");
}
__device__ __forceinline__ u64 shfl_xor64(u64 v, int off){
    uint32_t lo = (uint32_t)v, hi = (uint32_t)(v >> 32);
    lo = __shfl_xor_sync(0xffffffffu, lo, off);
    hi = __shfl_xor_sync(0xffffffffu, hi, off);
    return ((u64)hi << 32) | lo;
}

// ============ pack: weight/proto relayouts ============
__global__ void pack_kernel(const float* __restrict__ proto,
                            const float* __restrict__ Wf, const float* __restrict__ Wi,
                            const float* __restrict__ Wg, const float* __restrict__ Wo){
    int idx = blockIdx.x * blockDim.x + threadIdx.x;
    if (idx < HID*NPROTO){
        int h = idx >> 7, pp = idx & (NPROTO-1);
        g_Wpack[pp][h] = make_float4(Wf[idx], Wi[idx], Wg[idx], Wo[idx]);
    }
    if (idx < (DHTOT/4)*NPROTO){
        int q = idx >> 7, pp = idx & (NPROTO-1);
        const float* pr = proto + pp*DHTOT + 4*q;
        g_protoPack[q][pp] = make_float4(pr[0], pr[1], pr[2], pr[3]);
    }
    if (idx < DIN*(NPROTO/2)){
        int d = idx >> 6, pp = idx & 63;
        g_PP[d][pp] = pk2(proto[(2*pp)*DHTOT + d], proto[(2*pp+1)*DHTOT + d]);
    }
    if (idx < NPROTO){
        float s = 0.f;
        for (int d = 0; d < DHTOT; ++d){ float v = proto[idx*DHTOT + d]; s = fmaf(v, v, s); }
        g_pn2[idx] = s;
    }
}

// ============ precompute DOTX = dot(x, proto_x) - 0.5*||x||^2 ============
// grid: (T*B)/128 blocks, 512 threads. thread=(rp = rowpair, pg): 2 rows x 16 p.
extern __shared__ char psm[];
__global__ __launch_bounds__(512, 1)
void dotx_kernel(const float* __restrict__ x){
    u64* PPs = reinterpret_cast<u64*>(psm);        // [128 d][64 pp]
    const int tid = threadIdx.x;
    const int lane = tid & 31, wrp = tid >> 5;
    // stage PP (64 KB)
    #pragma unroll
    for (int i = 0; i < 16; ++i)
        PPs[tid + i*512] = ((const u64*)g_PP)[tid + i*512];
    __syncthreads();

    const int pg = lane & 7;                       // pp = i*8 + pg
    const int rp = (wrp << 2) | (lane >> 3);       // 0..63
    const size_t r0 = (size_t)blockIdx.x*128 + rp*2;
    const float4* xr0 = reinterpret_cast<const float4*>(x + r0*DIN);
    const float4* xr1 = reinterpret_cast<const float4*>(x + (r0+1)*DIN);

    u64 accA[8], accB[8];
    #pragma unroll
    for (int i = 0; i < 8; ++i){ accA[i] = 0ull; accB[i] = 0ull; }
    float n0 = 0.f, n1 = 0.f;

    #pragma unroll 4
    for (int dq = 0; dq < 32; ++dq){
        float4 fa = __ldcg(&xr0[dq]);
        float4 fb = __ldcg(&xr1[dq]);
        const float a[4] = {fa.x, fa.y, fa.z, fa.w};
        const float b[4] = {fb.x, fb.y, fb.z, fb.w};
        #pragma unroll
        for (int l = 0; l < 4; ++l){
            int d = dq*4 + l;
            u64 va = pk2(a[l], a[l]);
            u64 vb = pk2(b[l], b[l]);
            n0 = fmaf(a[l], a[l], n0);
            n1 = fmaf(b[l], b[l], n1);
            const u64* row = PPs + d*64 + pg;
            #pragma unroll
            for (int i = 0; i < 8; ++i){
                u64 pv = row[i*8];
                accA[i] = ffma2(va, pv, accA[i]);
                accB[i] = ffma2(vb, pv, accB[i]);
            }
        }
    }
    u64 nA2 = pk2(-0.5f*n0, -0.5f*n0);
    u64 nB2 = pk2(-0.5f*n1, -0.5f*n1);
    u64* DX = reinterpret_cast<u64*>(g_DOTX);
    #pragma unroll
    for (int i = 0; i < 8; ++i){
        int pp = i*8 + pg;
        DX[r0*64 + pp]     = add2(accA[i], nA2);
        DX[(r0+1)*64 + pp] = add2(accB[i], nB2);
    }
}

// ============ recurrent kernel ============
extern __shared__ char sm[];

__global__ void __cluster_dims__(CSZ,1,1) __launch_bounds__(NTHR, 1)
qlstm_kernel(const float* __restrict__ bf, const float* __restrict__ bi,
             const float* __restrict__ bg, const float* __restrict__ bo,
             float* __restrict__ out){
    const int tid  = threadIdx.x;
    const int lane = tid & 31;
    const int wrp  = tid >> 5;
    const uint32_t rank = ctarank();
    const int bbase = (blockIdx.x >> 2) * NB;
    const uint32_t base = smem_u32(sm);

    float4* PROT = reinterpret_cast<float4*>(sm + PROT_OFF);   // [16 q][128 p]
    u64*    PGp  = reinterpret_cast<u64*>(sm + PG_OFF);
    u64*    KD   = reinterpret_cast<u64*>(sm + KD_OFF);        // [p][10]
    const ulonglong2* KDv2 = reinterpret_cast<const ulonglong2*>(sm + KD_OFF);
    u64*    DOT  = reinterpret_cast<u64*>(sm + DOT_OFF);
    u64*    PD   = reinterpret_cast<u64*>(sm + PD_OFF);        // [4 dc][4 pr][128 p]
    u64*    CN2  = reinterpret_cast<u64*>(sm + CN2_OFF);
    u64*    CMB  = reinterpret_cast<u64*>(sm + CMB_OFF);       // [4 pr][64 h]
    float*  CMBF = reinterpret_cast<float*>(sm + CMB_OFF);

    // roles
    const int pK  = tid & 127;          // dist p / k p
    const int dcD = tid >> 7;           // dist h-chunk (0..3), 16 h each
    const int prK = tid >> 7;           // k batch-pair
    const int hL  = tid & 63;           // gate/reduce h_local
    const int pcG = tid >> 6;           // gate p-chunk (0..7)
    const int bR  = tid >> 6;           // reduce batch (0..7)
    const int hglob = (int)rank*64 + hL;

    // ---------- preamble ----------
    // prototype h-quarter -> smem: global q = 32 + rank*16 + q_local
    #pragma unroll
    for (int i = 0; i < 4; ++i){
        int idx = tid + i*NTHR;         // 0..2047
        int q = idx >> 7, p = idx & 127;
        PROT[q*128 + p] = g_protoPack[32 + (int)rank*16 + q][p];
    }
    // register weights: thread (hL, pcG) holds p = pcG*16 + j
    u64 wFI[16], wGO[16];
    #pragma unroll
    for (int j = 0; j < 16; ++j){
        float4 w = g_Wpack[pcG*16 + j][hglob];
        wFI[j] = pk2(w.x, w.y);
        wGO[j] = pk2(w.z, w.w);
    }
    // zero hv
    if (tid < 256) CMB[tid] = 0ull;

    const u64 bFI = pk2(bf[hglob], bi[hglob]);
    const u64 bGO = pk2(bg[hglob], bo[hglob]);
    const float pn2v = g_pn2[pK];

    // DSMEM addresses
    uint32_t dotAddr[CSZ], cnAddr[CSZ];
    {
        uint32_t dOff = base + DOT_OFF + (uint32_t)((((rank*4) + prK)*128 + pK)*8);
        uint32_t cOff = base + CN2_OFF + (uint32_t)((rank*4 + wrp)*8);   // cn2 role (tid<128)
        #pragma unroll
        for (uint32_t r = 0; r < CSZ; ++r){
            dotAddr[r] = mapa_u32(dOff, r);
            cnAddr[r]  = mapa_u32(cOff, r);
        }
    }

    const float* __restrict__ dxbase = g_DOTX + (size_t)(bbase + 2*prK)*NPROTO + pK;

    float cx = 0.f, hv = 0.f;

    __syncthreads();
    cl_arrive(); cl_wait();

    for (int t = 0; t < TSTEPS; ++t){
        const uint32_t bufDot = (uint32_t)(t & 1) * 16384u;
        const uint32_t bufCn  = (uint32_t)(t & 1) * 128u;
        const int      bufU   = (t & 1) * 2048;
        const int      bufC   = (t & 1) * 16;

        // prefetch DOTX for this step (consumed ~2000 cyc later in k-phase)
        const float* dxp = dxbase + (size_t)t*BSZ*NPROTO;
        float dxa = __ldcg(dxp);
        float dxb = __ldcg(dxp + NPROTO);

        __syncthreads();                // S1: hv(t-1) visible locally

        // ---- dist over h-quarter: thread=(pK, dcD), 16 h, all 4 pairs ----
        {
            u64 acc0 = 0ull, acc1 = 0ull, acc2 = 0ull, acc3 = 0ull;
            const float4* pp = PROT + (dcD*4)*128 + pK;
            const ulonglong2* cb = reinterpret_cast<const ulonglong2*>(CMB + dcD*16);
            #pragma unroll
            for (int i = 0; i < 4; ++i){
                float4 pv = pp[i*128];
                u64 v0 = pk2(pv.x, pv.x), v1 = pk2(pv.y, pv.y);
                u64 v2 = pk2(pv.z, pv.z), v3 = pk2(pv.w, pv.w);
                #pragma unroll
                for (int pr = 0; pr < 4; ++pr){
                    ulonglong2 cA = cb[pr*32 + i*2    ];
                    ulonglong2 cB = cb[pr*32 + i*2 + 1];
                    u64 acc = (pr==0)?acc0:(pr==1)?acc1:(pr==2)?acc2:acc3;
                    acc = ffma2(cA.x, v0, acc);
                    acc = ffma2(cA.y, v1, acc);
                    acc = ffma2(cB.x, v2, acc);
                    acc = ffma2(cB.y, v3, acc);
                    if (pr==0) acc0=acc; else if (pr==1) acc1=acc; else if (pr==2) acc2=acc; else acc3=acc;
                }
            }
            PD[(dcD*4 + 0)*128 + pK] = acc0;
            PD[(dcD*4 + 1)*128 + pK] = acc1;
            PD[(dcD*4 + 2)*128 + pK] = acc2;
            PD[(dcD*4 + 3)*128 + pK] = acc3;
        }

        // ---- cn2_h partial (warps 0-3, pr = wrp) ----
        if (tid < 128){
            const u64* cb = CMB + wrp*64;
            u64 c0 = cb[lane], c1 = cb[lane + 32];
            u64 a = ffma2(c0, c0, ffma2(c1, c1, 0ull));
            #pragma unroll
            for (int off = 16; off; off >>= 1)
                a = add2(a, shfl_xor64(a, off));
            if (lane == 0){
                #pragma unroll
                for (int r = 0; r < CSZ; ++r) st_cl64(cnAddr[r] + bufCn, a);
            }
        }
        __syncthreads();                // S2: PD complete

        // ---- sum dc partials + broadcast: thread=(pK, prK) ----
        {
            u64 s =        PD[(0*4 + prK)*128 + pK];
            s = add2(s,    PD[(1*4 + prK)*128 + pK]);
            s = add2(s,    PD[(2*4 + prK)*128 + pK]);
            s = add2(s,    PD[(3*4 + prK)*128 + pK]);
            #pragma unroll
            for (int r = 0; r < CSZ; ++r) st_cl64(dotAddr[r] + bufDot, s);
        }
        cl_arrive();
        cl_wait();                      // all ranks' partials visible

        // ---- k: reduce ranks + DOTX + exp ----
        {
            const u64* db = DOT + bufU;
            u64 ds =        db[(0*4 + prK)*128 + pK];
            ds = add2(ds,   db[(1*4 + prK)*128 + pK]);
            ds = add2(ds,   db[(2*4 + prK)*128 + pK]);
            ds = add2(ds,   db[(3*4 + prK)*128 + pK]);
            const u64* cn = CN2 + bufC;
            u64 cs = add2(add2(cn[0*4 + prK], cn[1*4 + prK]),
                          add2(cn[2*4 + prK], cn[3*4 + prK]));
            float d0, d1, c0, c1;
            upk2(ds, d0, d1); upk2(cs, c0, c1);
            float k0 = __expf(2.f*(d0 + dxa) - pn2v - c0);
            float k1 = __expf(2.f*(d1 + dxb) - pn2v - c1);
            ulonglong2 kk; kk.x = pk2(k0, k0); kk.y = pk2(k1, k1);
            *reinterpret_cast<ulonglong2*>(KD + pK*10 + 2*prK) = kk;
        }
        __syncthreads();                // S3: KD ready

        // ---- gate GEMM (R4-proven): thread=(hL, pcG), 16 p, 8 batches ----
        {
            u64 F0=0,F1=0,F2=0,F3=0,F4=0,F5=0,F6=0,F7=0;
            u64 G0=0,G1=0,G2=0,G3=0,G4=0,G5=0,G6=0,G7=0;
            const ulonglong2* kp = KDv2 + (pcG*16)*5;   // KD row = 10 u64 = 5 u128
            #pragma unroll 4
            for (int j = 0; j < 16; ++j){
                ulonglong2 kA = kp[j*5 + 0];
                ulonglong2 kB = kp[j*5 + 1];
                ulonglong2 kC = kp[j*5 + 2];
                ulonglong2 kE = kp[j*5 + 3];
                F0 = ffma2(wFI[j], kA.x, F0);  G0 = ffma2(wGO[j], kA.x, G0);
                F1 = ffma2(wFI[j], kA.y, F1);  G1 = ffma2(wGO[j], kA.y, G1);
                F2 = ffma2(wFI[j], kB.x, F2);  G2 = ffma2(wGO[j], kB.x, G2);
                F3 = ffma2(wFI[j], kB.y, F3);  G3 = ffma2(wGO[j], kB.y, G3);
                F4 = ffma2(wFI[j], kC.x, F4);  G4 = ffma2(wGO[j], kC.x, G4);
                F5 = ffma2(wFI[j], kC.y, F5);  G5 = ffma2(wGO[j], kC.y, G5);
                F6 = ffma2(wFI[j], kE.x, F6);  G6 = ffma2(wGO[j], kE.x, G6);
                F7 = ffma2(wFI[j], kE.y, F7);  G7 = ffma2(wGO[j], kE.y, G7);
            }
            u64* pg = PGp + (pcG*8)*2*64 + hL;
            pg[(0*2+0)*64] = F0; pg[(0*2+1)*64] = G0;
            pg[(1*2+0)*64] = F1; pg[(1*2+1)*64] = G1;
            pg[(2*2+0)*64] = F2; pg[(2*2+1)*64] = G2;
            pg[(3*2+0)*64] = F3; pg[(3*2+1)*64] = G3;
            pg[(4*2+0)*64] = F4; pg[(4*2+1)*64] = G4;
            pg[(5*2+0)*64] = F5; pg[(5*2+1)*64] = G5;
            pg[(6*2+0)*64] = F6; pg[(6*2+1)*64] = G6;
            pg[(7*2+0)*64] = F7; pg[(7*2+1)*64] = G7;
        }
        __syncthreads();                // S4: PG ready

        // ---- reduce + activations: thread=(hL, bR) ----
        {
            u64 Fa = bFI, Ga = bGO;
            #pragma unroll
            for (int c = 0; c < 8; ++c){
                Fa = add2(Fa, PGp[((c*8 + bR)*2 + 0)*64 + hL]);
                Ga = add2(Ga, PGp[((c*8 + bR)*2 + 1)*64 + hL]);
            }
            float fp, ip, gp, op;
            upk2(Fa, fp, ip); upk2(Ga, gp, op);
            float fv = sigmf(fp), iv = sigmf(ip), gv = tanhf_(gp), ov = sigmf(op);
            cx = fv*cx + iv*gv;
            hv = ov * tanhf_(cx);
            CMBF[((bR >> 1)*64 + hL)*2 + (bR & 1)] = hv;
            out[((size_t)t*BSZ + bbase + bR)*HID + hglob] = hv;
        }
        // loop-top S1 orders hv before next dist; DOT/CN2 double-buffer +
        // single cluster barrier per step handles cross-CTA WAR.
    }

    // ---- finals ----
    {
        const size_t TBH = (size_t)TSTEPS * BSZ * HID;
        const size_t BH  = (size_t)BSZ * HID;
        out[TBH + (size_t)(bbase + bR)*HID + hglob] = hv;
        out[TBH + BH + (size_t)(bbase + bR)*HID + hglob] = cx;
    }
}

extern "C" void kernel_launch(void* const* d_in, const int* in_sizes, int n_in,
                              void* d_out, int out_size){
    (void)in_sizes; (void)n_in; (void)out_size;
    const float* inputs = (const float*)d_in[0];
    const float* proto  = (const float*)d_in[1];
    const float* Wf     = (const float*)d_in[2];
    const float* bf     = (const float*)d_in[3];
    const float* Wi     = (const float*)d_in[4];
    const float* bi     = (const float*)d_in[5];
    const float* Wg     = (const float*)d_in[6];
    const float* bg     = (const float*)d_in[7];
    const float* Wo     = (const float*)d_in[8];
    const float* bo     = (const float*)d_in[9];
    float* out = (float*)d_out;

    cudaFuncSetAttribute(qlstm_kernel,
                         cudaFuncAttributeMaxDynamicSharedMemorySize, SMEM_TOTAL);
    cudaFuncSetAttribute(dotx_kernel,
                         cudaFuncAttributeMaxDynamicSharedMemorySize, 65536);

    pack_kernel<<<(HID*NPROTO + 511)/512, 512>>>(proto, Wf, Wi, Wg, Wo);
    dotx_kernel<<<(TSTEPS*BSZ)/128, 512, 65536>>>(inputs);
    qlstm_kernel<<<NCTA, NTHR, SMEM_TOTAL>>>(bf, bi, bg, bo, out);
}